// round 4
// baseline (speedup 1.0000x reference)
#include <cuda_runtime.h>
#include <cstdint>

// ---------------------------------------------------------------------------
// B=2, N=1024, D=1024, K=8 (circulant), H=16, dh=64
// circ_linear == dense GEMM with W[p*8+i][q*8+j] = w[p,q,(i-j) mod 8]
// ---------------------------------------------------------------------------
constexpr int DD = 1024;
constexpr int MM = 2048;

__device__ float g_We[4][DD * DD];   // expanded weights, layout B[k][n]
__device__ float g_Q[MM * DD];
__device__ float g_K[MM * DD];
__device__ float g_V[MM * DD];
__device__ float g_O[MM * DD];
__device__ float g_P[6][MM * DD];    // split-K partials

__device__ __forceinline__ uint32_t f2tf32(float f) {
    uint32_t r;
    asm("cvt.rna.tf32.f32 %0, %1;" : "=r"(r) : "f"(f));
    return r;
}

#define MMA_TF32(ACC, AF, BF)                                            \
    asm volatile(                                                        \
        "mma.sync.aligned.m16n8k8.row.col.f32.tf32.tf32.f32 "            \
        "{%0,%1,%2,%3}, {%4,%5,%6,%7}, {%8,%9}, {%0,%1,%2,%3};"          \
        : "+f"((ACC)[0]), "+f"((ACC)[1]), "+f"((ACC)[2]), "+f"((ACC)[3]) \
        : "r"((AF)[0]), "r"((AF)[1]), "r"((AF)[2]), "r"((AF)[3]),        \
          "r"((BF)[0]), "r"((BF)[1]))

// ---------------------------------------------------------------------------
// Expand circulant blocks: dst[k][n] = w[n/8][k/8][(n-k)&7]
// ---------------------------------------------------------------------------
__global__ void expand_kernel(const float* __restrict__ w0,
                              const float* __restrict__ w1,
                              const float* __restrict__ w2,
                              const float* __restrict__ w3)
{
    const float* w;
    switch (blockIdx.y) {
        case 0:  w = w0; break;
        case 1:  w = w1; break;
        case 2:  w = w2; break;
        default: w = w3; break;
    }
    float* dst = g_We[blockIdx.y];
    int idx = blockIdx.x * 256 + threadIdx.x;
    int k = idx >> 10;
    int n = idx & 1023;
    dst[idx] = w[((n >> 3) << 10) + ((k >> 3) << 3) + ((n - k) & 7)];
}

// ---------------------------------------------------------------------------
// TF32 GEMM, split-K=2, partial outputs (no bias).
// blockIdx.z = mat*2 + split. B = Bbase + mat*matStride.
// Partial = g_P[blockIdx.z]. K-range: [split*512, split*512+512).
// CTA tile 128x128, 8 warps of 32x64, BK=16 double-buffered.
// ---------------------------------------------------------------------------
constexpr int AST = 20;
constexpr int BST = 136;

__global__ __launch_bounds__(256, 2)
void gemm_tf32(const float* __restrict__ A,
               const float* __restrict__ Bbase, int matStride)
{
    const int mat   = blockIdx.z >> 1;
    const int split = blockIdx.z & 1;
    const float* Bm = Bbase + (size_t)mat * matStride;
    float* C = g_P[blockIdx.z];
    const int kBeg = split * 512;

    __shared__ uint32_t As[2][128 * AST];
    __shared__ uint32_t Bs[2][16 * BST];

    const int tid  = threadIdx.x;
    const int warp = tid >> 5;
    const int lane = tid & 31;
    const int grp  = lane >> 2;
    const int q    = lane & 3;

    const int cRow = blockIdx.y * 128;
    const int cCol = blockIdx.x * 128;
    const int wm   = (warp & 3) * 32;
    const int wn   = (warp >> 2) * 64;

    const int am = tid >> 2;
    const int ak = (tid & 3) * 4;
    const int bkRow = tid >> 5;
    const int bn = lane * 4;

    const float* Ap = A  + (size_t)(cRow + am) * DD + kBeg + ak;
    const float* Bp = Bm + (size_t)(kBeg + bkRow) * DD + cCol + bn;

    float acc[2][8][4];
#pragma unroll
    for (int mi = 0; mi < 2; mi++)
#pragma unroll
        for (int ni = 0; ni < 8; ni++)
#pragma unroll
            for (int c = 0; c < 4; c++) acc[mi][ni][c] = 0.f;

    {
        float4 a0 = *(const float4*)(Ap);
        float4 a1 = *(const float4*)(Ap + 64 * DD);
        float4 b0 = *(const float4*)(Bp);
        float4 b1 = *(const float4*)(Bp + 8 * DD);
        *(uint4*)&As[0][am * AST + ak] =
            make_uint4(f2tf32(a0.x), f2tf32(a0.y), f2tf32(a0.z), f2tf32(a0.w));
        *(uint4*)&As[0][(am + 64) * AST + ak] =
            make_uint4(f2tf32(a1.x), f2tf32(a1.y), f2tf32(a1.z), f2tf32(a1.w));
        *(uint4*)&Bs[0][bkRow * BST + bn] =
            make_uint4(f2tf32(b0.x), f2tf32(b0.y), f2tf32(b0.z), f2tf32(b0.w));
        *(uint4*)&Bs[0][(bkRow + 8) * BST + bn] =
            make_uint4(f2tf32(b1.x), f2tf32(b1.y), f2tf32(b1.z), f2tf32(b1.w));
    }
    __syncthreads();

    int buf = 0;
    for (int k0 = 0; k0 < 512; k0 += 16) {
        const bool has_next = (k0 + 16 < 512);
        float4 pa0, pa1, pb0, pb1;
        if (has_next) {
            const int kn = k0 + 16;
            pa0 = *(const float4*)(Ap + kn);
            pa1 = *(const float4*)(Ap + 64 * DD + kn);
            pb0 = *(const float4*)(Bp + (size_t)kn * DD);
            pb1 = *(const float4*)(Bp + (size_t)(kn + 8) * DD);
        }

        const uint32_t* as = As[buf];
        const uint32_t* bs = Bs[buf];

        // ---- fragment-pipelined: af for BOTH k-halves, bf staged ----
        uint32_t af[2][2][4];
#pragma unroll
        for (int kk = 0; kk < 2; kk++)
#pragma unroll
            for (int mi = 0; mi < 2; mi++) {
                int m = wm + mi * 16 + grp;
                af[kk][mi][0] = as[m * AST + kk * 8 + q];
                af[kk][mi][1] = as[(m + 8) * AST + kk * 8 + q];
                af[kk][mi][2] = as[m * AST + kk * 8 + q + 4];
                af[kk][mi][3] = as[(m + 8) * AST + kk * 8 + q + 4];
            }
        uint32_t bf[8][2];
#pragma unroll
        for (int ni = 0; ni < 8; ni++) {
            bf[ni][0] = bs[q * BST + wn + ni * 8 + grp];
            bf[ni][1] = bs[(q + 4) * BST + wn + ni * 8 + grp];
        }
        uint32_t bf1[8][2];
#pragma unroll
        for (int ni = 0; ni < 8; ni++) {
            bf1[ni][0] = bs[(8 + q) * BST + wn + ni * 8 + grp];
            bf1[ni][1] = bs[(8 + q + 4) * BST + wn + ni * 8 + grp];
        }
#pragma unroll
        for (int mi = 0; mi < 2; mi++)
#pragma unroll
            for (int ni = 0; ni < 8; ni++)
                MMA_TF32(acc[mi][ni], af[0][mi], bf[ni]);
#pragma unroll
        for (int mi = 0; mi < 2; mi++)
#pragma unroll
            for (int ni = 0; ni < 8; ni++)
                MMA_TF32(acc[mi][ni], af[1][mi], bf1[ni]);

        if (has_next) {
            uint32_t* asn = As[buf ^ 1];
            uint32_t* bsn = Bs[buf ^ 1];
            *(uint4*)&asn[am * AST + ak] =
                make_uint4(f2tf32(pa0.x), f2tf32(pa0.y), f2tf32(pa0.z), f2tf32(pa0.w));
            *(uint4*)&asn[(am + 64) * AST + ak] =
                make_uint4(f2tf32(pa1.x), f2tf32(pa1.y), f2tf32(pa1.z), f2tf32(pa1.w));
            *(uint4*)&bsn[bkRow * BST + bn] =
                make_uint4(f2tf32(pb0.x), f2tf32(pb0.y), f2tf32(pb0.z), f2tf32(pb0.w));
            *(uint4*)&bsn[(bkRow + 8) * BST + bn] =
                make_uint4(f2tf32(pb1.x), f2tf32(pb1.y), f2tf32(pb1.z), f2tf32(pb1.w));
            __syncthreads();
            buf ^= 1;
        }
    }

#pragma unroll
    for (int mi = 0; mi < 2; mi++) {
#pragma unroll
        for (int ni = 0; ni < 8; ni++) {
            int row = cRow + wm + mi * 16 + grp;
            int col = cCol + wn + ni * 8 + q * 2;
            *(float2*)(C + (size_t)row * DD + col) =
                make_float2(acc[mi][ni][0], acc[mi][ni][1]);
            *(float2*)(C + (size_t)(row + 8) * DD + col) =
                make_float2(acc[mi][ni][2], acc[mi][ni][3]);
        }
    }
}

// ---------------------------------------------------------------------------
// Split-K reduce + bias.  out = p0 + p1 + bias[col]
// grid.x covers MM*DD/1024 blocks of 256 threads x float4; grid.y = matrix.
// ---------------------------------------------------------------------------
__global__ __launch_bounds__(256)
void reduce_bias(const float* __restrict__ bi0, const float* __restrict__ bi1,
                 const float* __restrict__ bi2,
                 float* __restrict__ o0, float* __restrict__ o1,
                 float* __restrict__ o2)
{
    const int mat = blockIdx.y;
    const float* bias = (mat == 0) ? bi0 : (mat == 1) ? bi1 : bi2;
    float* out = (mat == 0) ? o0 : (mat == 1) ? o1 : o2;
    const float* p0 = g_P[mat * 2];
    const float* p1 = g_P[mat * 2 + 1];

    int idx = (blockIdx.x * 256 + threadIdx.x) * 4;
    float4 a = *(const float4*)(p0 + idx);
    float4 b = *(const float4*)(p1 + idx);
    int col = idx & 1023;
    float4 bv = *(const float4*)(bias + col);
    float4 r;
    r.x = a.x + b.x + bv.x;
    r.y = a.y + b.y + bv.y;
    r.z = a.z + b.z + bv.z;
    r.w = a.w + b.w + bv.w;
    *(float4*)(out + idx) = r;
}

// ---------------------------------------------------------------------------
// Tensor-core causal flash attention (TF32 mma) — unchanged from R3.
// ---------------------------------------------------------------------------
constexpr int KST = 68;
constexpr int VST = 72;

__global__ __launch_bounds__(128, 3)
void flash_mma(const float* __restrict__ Qg, const float* __restrict__ Kg,
               const float* __restrict__ Vg, float* __restrict__ Og)
{
    __shared__ uint32_t Ksm[64 * KST];
    __shared__ uint32_t Vsm[64 * VST];

    const int tid  = threadIdx.x;
    const int warp = tid >> 5;
    const int lane = tid & 31;
    const int grp  = lane >> 2;
    const int q    = lane & 3;

    const int qb = 15 - blockIdx.y;
    const int i0 = qb * 64;
    const int h  = blockIdx.x & 15;
    const int b  = blockIdx.x >> 4;
    const size_t base = (size_t)b * (1024 * 1024) + h * 64;

    const int wm = warp * 16;
    const int r0 = i0 + wm + grp;

#pragma unroll
    for (int it = 0; it < 8; it++) {
        int idx = tid + it * 128;
        int row = idx >> 4;
        int c4  = (idx & 15) << 2;
        *(float4*)&((float*)Vsm)[row * VST + c4] =
            *(const float4*)(Qg + base + (size_t)(i0 + row) * DD + c4);
    }
    __syncthreads();
    uint32_t qf[8][4];
    {
        const float* Qs = (const float*)Vsm;
#pragma unroll
        for (int ks = 0; ks < 8; ks++) {
            qf[ks][0] = f2tf32(Qs[(wm + grp)     * VST + ks * 8 + q]);
            qf[ks][1] = f2tf32(Qs[(wm + grp + 8) * VST + ks * 8 + q]);
            qf[ks][2] = f2tf32(Qs[(wm + grp)     * VST + ks * 8 + q + 4]);
            qf[ks][3] = f2tf32(Qs[(wm + grp + 8) * VST + ks * 8 + q + 4]);
        }
    }
    __syncthreads();

    float oacc[8][4];
#pragma unroll
    for (int nt = 0; nt < 8; nt++)
#pragma unroll
        for (int c = 0; c < 4; c++) oacc[nt][c] = 0.f;
    float m0 = -1e30f, m1 = -1e30f, l0 = 0.f, l1 = 0.f;

    for (int jb = 0; jb <= qb; jb++) {
        const int j0 = jb * 64;

#pragma unroll
        for (int it = 0; it < 8; it++) {
            int idx = tid + it * 128;
            int row = idx >> 4;
            int c4  = (idx & 15) << 2;
            float4 k4 = *(const float4*)(Kg + base + (size_t)(j0 + row) * DD + c4);
            float4 v4 = *(const float4*)(Vg + base + (size_t)(j0 + row) * DD + c4);
            *(uint4*)&Ksm[row * KST + c4] =
                make_uint4(f2tf32(k4.x), f2tf32(k4.y), f2tf32(k4.z), f2tf32(k4.w));
            *(uint4*)&Vsm[row * VST + c4] =
                make_uint4(f2tf32(v4.x), f2tf32(v4.y), f2tf32(v4.z), f2tf32(v4.w));
        }
        __syncthreads();

        float sacc[8][4];
#pragma unroll
        for (int nt = 0; nt < 8; nt++)
#pragma unroll
            for (int c = 0; c < 4; c++) sacc[nt][c] = 0.f;
#pragma unroll
        for (int ks = 0; ks < 8; ks++) {
            uint32_t bf[8][2];
#pragma unroll
            for (int nt = 0; nt < 8; nt++) {
                bf[nt][0] = Ksm[(nt * 8 + grp) * KST + ks * 8 + q];
                bf[nt][1] = Ksm[(nt * 8 + grp) * KST + ks * 8 + q + 4];
            }
#pragma unroll
            for (int nt = 0; nt < 8; nt++)
                MMA_TF32(sacc[nt], qf[ks], bf[nt]);
        }

        const bool diag = (jb == qb);
        float mx0 = -1e30f, mx1 = -1e30f;
#pragma unroll
        for (int nt = 0; nt < 8; nt++) {
            float s0 = sacc[nt][0] * 0.125f;
            float s1 = sacc[nt][1] * 0.125f;
            float s2 = sacc[nt][2] * 0.125f;
            float s3 = sacc[nt][3] * 0.125f;
            if (diag) {
                int j = j0 + nt * 8 + q * 2;
                if (j     > r0)     s0 = -1e30f;
                if (j + 1 > r0)     s1 = -1e30f;
                if (j     > r0 + 8) s2 = -1e30f;
                if (j + 1 > r0 + 8) s3 = -1e30f;
            }
            sacc[nt][0] = s0; sacc[nt][1] = s1;
            sacc[nt][2] = s2; sacc[nt][3] = s3;
            mx0 = fmaxf(mx0, fmaxf(s0, s1));
            mx1 = fmaxf(mx1, fmaxf(s2, s3));
        }
        mx0 = fmaxf(mx0, __shfl_xor_sync(0xffffffffu, mx0, 1));
        mx0 = fmaxf(mx0, __shfl_xor_sync(0xffffffffu, mx0, 2));
        mx1 = fmaxf(mx1, __shfl_xor_sync(0xffffffffu, mx1, 1));
        mx1 = fmaxf(mx1, __shfl_xor_sync(0xffffffffu, mx1, 2));
        float mn0 = fmaxf(m0, mx0), mn1 = fmaxf(m1, mx1);
        float al0 = __expf(m0 - mn0), al1 = __expf(m1 - mn1);
        m0 = mn0; m1 = mn1;
        float ps0 = 0.f, ps1 = 0.f;
#pragma unroll
        for (int nt = 0; nt < 8; nt++) {
            float p0 = __expf(sacc[nt][0] - mn0);
            float p1 = __expf(sacc[nt][1] - mn0);
            float p2 = __expf(sacc[nt][2] - mn1);
            float p3 = __expf(sacc[nt][3] - mn1);
            ps0 += p0 + p1;
            ps1 += p2 + p3;
            sacc[nt][0] = p0; sacc[nt][1] = p1;
            sacc[nt][2] = p2; sacc[nt][3] = p3;
        }
        l0 = l0 * al0 + ps0;
        l1 = l1 * al1 + ps1;
#pragma unroll
        for (int nt = 0; nt < 8; nt++) {
            oacc[nt][0] *= al0; oacc[nt][1] *= al0;
            oacc[nt][2] *= al1; oacc[nt][3] *= al1;
        }

        __syncthreads();

        uint32_t* Psm = Ksm + wm * KST;
#pragma unroll
        for (int nt = 0; nt < 8; nt++) {
            *(uint2*)&Psm[grp * KST + nt * 8 + q * 2] =
                make_uint2(f2tf32(sacc[nt][0]), f2tf32(sacc[nt][1]));
            *(uint2*)&Psm[(grp + 8) * KST + nt * 8 + q * 2] =
                make_uint2(f2tf32(sacc[nt][2]), f2tf32(sacc[nt][3]));
        }
        __syncwarp();

#pragma unroll
        for (int ks = 0; ks < 8; ks++) {
            uint32_t af[4];
            af[0] = Psm[grp * KST + ks * 8 + q];
            af[1] = Psm[(grp + 8) * KST + ks * 8 + q];
            af[2] = Psm[grp * KST + ks * 8 + q + 4];
            af[3] = Psm[(grp + 8) * KST + ks * 8 + q + 4];
            uint32_t bf[8][2];
#pragma unroll
            for (int nt = 0; nt < 8; nt++) {
                bf[nt][0] = Vsm[(ks * 8 + q) * VST + nt * 8 + grp];
                bf[nt][1] = Vsm[(ks * 8 + q + 4) * VST + nt * 8 + grp];
            }
#pragma unroll
            for (int nt = 0; nt < 8; nt++)
                MMA_TF32(oacc[nt], af, bf[nt]);
        }
        __syncthreads();
    }

    l0 += __shfl_xor_sync(0xffffffffu, l0, 1);
    l0 += __shfl_xor_sync(0xffffffffu, l0, 2);
    l1 += __shfl_xor_sync(0xffffffffu, l1, 1);
    l1 += __shfl_xor_sync(0xffffffffu, l1, 2);
    const float inv0 = 1.f / l0;
    const float inv1 = 1.f / l1;
#pragma unroll
    for (int nt = 0; nt < 8; nt++) {
        int col = nt * 8 + q * 2;
        *(float2*)(Og + base + (size_t)r0 * DD + col) =
            make_float2(oacc[nt][0] * inv0, oacc[nt][1] * inv0);
        *(float2*)(Og + base + (size_t)(r0 + 8) * DD + col) =
            make_float2(oacc[nt][2] * inv1, oacc[nt][3] * inv1);
    }
}

// ---------------------------------------------------------------------------
extern "C" void kernel_launch(void* const* d_in, const int* in_sizes, int n_in,
                              void* d_out, int out_size)
{
    (void)in_sizes; (void)n_in; (void)out_size;
    const float* x  = (const float*)d_in[0];
    const float* wq = (const float*)d_in[2];
    const float* bq = (const float*)d_in[3];
    const float* wk = (const float*)d_in[4];
    const float* bk = (const float*)d_in[5];
    const float* wv = (const float*)d_in[6];
    const float* bv = (const float*)d_in[7];
    const float* wo = (const float*)d_in[8];
    const float* bo = (const float*)d_in[9];
    float* out = (float*)d_out;

    float *We, *Qb, *Kb, *Vb, *Ob;
    cudaGetSymbolAddress((void**)&We, g_We);
    cudaGetSymbolAddress((void**)&Qb, g_Q);
    cudaGetSymbolAddress((void**)&Kb, g_K);
    cudaGetSymbolAddress((void**)&Vb, g_V);
    cudaGetSymbolAddress((void**)&Ob, g_O);

    expand_kernel<<<dim3(DD * DD / 256, 4), 256>>>(wq, wk, wv, wo);

    // QKV projections: split-K=2, partials in g_P[0..5]
    gemm_tf32<<<dim3(DD / 128, MM / 128, 6), 256>>>(x, We, DD * DD);
    reduce_bias<<<dim3(MM * DD / 1024, 3), 256>>>(bq, bk, bv, Qb, Kb, Vb);

    flash_mma<<<dim3(32, 16), 128>>>(Qb, Kb, Vb, Ob);

    // Output projection: split-K=2, partials in g_P[0..1]
    gemm_tf32<<<dim3(DD / 128, MM / 128, 2), 256>>>(Ob, We + 3 * DD * DD, 0);
    reduce_bias<<<dim3(MM * DD / 1024, 1), 256>>>(bo, bo, bo, out, out, out);
}